// round 14
// baseline (speedup 1.0000x reference)
#include <cuda_runtime.h>
#include <cuda_fp16.h>
#include <math.h>

#define NMAX 50000
#define EMAX 800000
#define GMAX 500
#define HID  64
#define CAP  96   // padded CSR slots per node (Poisson(16) degree; P(>95)~1e-44)

// ---------------- device scratch (static, no runtime allocation) ----------
__device__ int     g_is64;             // 1 if index tensors are int64, 0 if int32
__device__ int     g_deg[NMAX];        // edge-count per node (NO self loop)
__device__ int     g_fill[NMAX];       // fill cursors
__device__ int     g_colp[NMAX * CAP]; // padded CSR: node's edges at [node*CAP, node*CAP+deg)
__device__ __half2 g_bufT[NMAX * 32];  // gathered operand, fp16 (dis-scaled h@W)
__device__ float   g_bufH[NMAX * HID]; // relu activations, fp32

// Branch on detected dtype. g_is64 is set before any consumer runs.
__device__ __forceinline__ int load_idx(const void* p, long long i) {
    if (g_is64) return (int)((const long long*)p)[i];
    return ((const int*)p)[i];
}

// ---------------- index dtype detection (1 block) ---------------------------
__global__ void detect_kernel(const int* __restrict__ ei32) {
    __shared__ int acc[256];
    int t = threadIdx.x;
    int v = 0;
    for (int k = t; k < 2048; k += 256) v |= ei32[2 * k + 1];
    acc[t] = v;
    __syncthreads();
    for (int off = 128; off > 0; off >>= 1) {
        if (t < off) acc[t] |= acc[t + off];
        __syncthreads();
    }
    if (t == 0) g_is64 = (acc[0] == 0) ? 1 : 0;
}

__global__ void deg_kernel(const void* __restrict__ ei, int e) {
    int i = blockIdx.x * blockDim.x + threadIdx.x;
    if (i < e) {
        int d = load_idx(ei, (long long)e + i);  // dst row of edge_index
        atomicAdd(&g_deg[d], 1);
    }
}

// Padded-slot CSR fill: no rowptr needed, one scattered 4B write per edge.
__global__ void fill_kernel(const void* __restrict__ ei, int e) {
    int i = blockIdx.x * blockDim.x + threadIdx.x;
    if (i >= e) return;
    int s = load_idx(ei, i);
    int d = load_idx(ei, (long long)e + i);
    int p = atomicAdd(&g_fill[d], 1);
    if (p < CAP) g_colp[d * CAP + p] = s;
}

// ---------------- dense 64x64 GEMM, register-blocked 4 rows x 16 cols ------
// T[row] = half( rsqrt(deg[row]+1) * (in[row] @ W) ).
// Each W float4 from smem feeds 16 FMAs (4 rows) -> FFMA:LDS = 16:1.
__global__ void __launch_bounds__(256) gemm64_kernel(
        const float* __restrict__ in, const float* __restrict__ W,
        __half2* __restrict__ outT, int n) {
    __shared__ float Ws[64 * 64];
    int tid = threadIdx.x;  // 256
#pragma unroll
    for (int i = 0; i < 16; ++i) Ws[tid + 256 * i] = W[tid + 256 * i];
    __syncthreads();

    int q    = tid & 3;    // column quarter: cols q*16 .. q*16+15
    int rg   = tid >> 2;   // row group 0..63
    int row0 = blockIdx.x * 256 + rg * 4;
    if (row0 >= n) return;
    bool full = (row0 + 3 < n);

    float acc[4][16];
#pragma unroll
    for (int r = 0; r < 4; ++r)
#pragma unroll
        for (int j = 0; j < 16; ++j) acc[r][j] = 0.f;

#pragma unroll 2
    for (int k4 = 0; k4 < 16; ++k4) {
        float4 xv[4];
#pragma unroll
        for (int r = 0; r < 4; ++r) {
            if (full || row0 + r < n)
                xv[r] = *reinterpret_cast<const float4*>(in + (row0 + r) * 64 + k4 * 4);
            else
                xv[r] = make_float4(0.f, 0.f, 0.f, 0.f);
        }
#pragma unroll
        for (int kk = 0; kk < 4; ++kk) {
            const float4* wr =
                reinterpret_cast<const float4*>(Ws + (k4 * 4 + kk) * 64 + q * 16);
            float4 w0 = wr[0], w1 = wr[1], w2 = wr[2], w3 = wr[3];
#pragma unroll
            for (int r = 0; r < 4; ++r) {
                float xk = (kk == 0) ? xv[r].x : (kk == 1) ? xv[r].y
                         : (kk == 2) ? xv[r].z : xv[r].w;
                acc[r][0]  += xk * w0.x;  acc[r][1]  += xk * w0.y;
                acc[r][2]  += xk * w0.z;  acc[r][3]  += xk * w0.w;
                acc[r][4]  += xk * w1.x;  acc[r][5]  += xk * w1.y;
                acc[r][6]  += xk * w1.z;  acc[r][7]  += xk * w1.w;
                acc[r][8]  += xk * w2.x;  acc[r][9]  += xk * w2.y;
                acc[r][10] += xk * w2.z;  acc[r][11] += xk * w2.w;
                acc[r][12] += xk * w3.x;  acc[r][13] += xk * w3.y;
                acc[r][14] += xk * w3.z;  acc[r][15] += xk * w3.w;
            }
        }
    }

#pragma unroll
    for (int r = 0; r < 4; ++r) {
        int row = row0 + r;
        if (!full && row >= n) break;
        float ds = rsqrtf((float)(g_deg[row] + 1));
        __half2 hh[8];
#pragma unroll
        for (int j2 = 0; j2 < 8; ++j2)
            hh[j2] = __floats2half2_rn(ds * acc[r][j2 * 2], ds * acc[r][j2 * 2 + 1]);
        uint4* o = reinterpret_cast<uint4*>(outT + row * 32 + q * 8);
        const uint4* hsrc = reinterpret_cast<const uint4*>(hh);
        o[0] = hsrc[0];
        o[1] = hsrc[1];
    }
}

// ---------------- aggregation: 2 nodes per warp (2 independent chains) -----
__global__ void agg_kernel(const __half2* __restrict__ t,
                           const float* __restrict__ bias,
                           float* __restrict__ outH, int n) {
    int warp = (blockIdx.x * blockDim.x + threadIdx.x) >> 5;
    int lane = threadIdx.x & 31;
    int sub  = lane >> 4;          // 0 or 1: which node of the pair
    int fl   = lane & 15;          // feature lane: owns features 4*fl..4*fl+3
    int node = warp * 2 + sub;
    if (node >= n) return;

    const uint2* tu = reinterpret_cast<const uint2*>(t);

    uint2 raw = tu[node * 16 + fl];
    float2 a0 = __half22float2(*reinterpret_cast<__half2*>(&raw.x));
    float2 a1 = __half22float2(*reinterpret_cast<__half2*>(&raw.y));

    const int* col = g_colp + node * CAP;
    int cnt = g_deg[node];
    for (int e = 0; e < cnt; ++e) {
        int s = col[e];
        uint2 r = tu[s * 16 + fl];
        float2 f0 = __half22float2(*reinterpret_cast<__half2*>(&r.x));
        float2 f1 = __half22float2(*reinterpret_cast<__half2*>(&r.y));
        a0.x += f0.x; a0.y += f0.y;
        a1.x += f1.x; a1.y += f1.y;
    }

    float d = rsqrtf((float)(cnt + 1));
    float4 b = *reinterpret_cast<const float4*>(bias + fl * 4);
    float4 r;
    r.x = fmaxf(d * a0.x + b.x, 0.f);
    r.y = fmaxf(d * a0.y + b.y, 0.f);
    r.z = fmaxf(d * a1.x + b.z, 0.f);
    r.w = fmaxf(d * a1.y + b.w, 0.f);
    *reinterpret_cast<float4*>(outH + node * 64 + fl * 4) = r;
}

// ---------------- fused agg3 + mean pool + MLP + log_softmax ---------------
__device__ __forceinline__ int lower_bound_batch(const void* batch, int n, int key) {
    int lo = 0, hi = n;
    while (lo < hi) {
        int mid = (lo + hi) >> 1;
        if (load_idx(batch, mid) < key) lo = mid + 1;
        else hi = mid;
    }
    return lo;
}

__global__ void pool_mlp_kernel(const __half2* __restrict__ t,
                                const void* __restrict__ batch, int n,
                                const float* __restrict__ b3,
                                const float* __restrict__ lin1W,
                                const float* __restrict__ lin1b,
                                const float* __restrict__ lin2W,
                                const float* __restrict__ lin2b,
                                float* __restrict__ out) {
    int g    = blockIdx.x;
    int tid  = threadIdx.x;  // 512
    int warp = tid >> 5;     // 0..15
    int lane = tid & 31;
    int sub  = lane >> 4;    // 0/1
    int fl   = lane & 15;    // feature lane
    int slot = warp * 2 + sub;  // 0..31

    __shared__ float psum[32][64];
    __shared__ float pooled[64];
    __shared__ float h1[64];
    __shared__ float logits[10];
    __shared__ float lse;
    __shared__ int   sbeg, send;

    if (tid == 0) sbeg = lower_bound_batch(batch, n, g);
    if (tid == 32) send = lower_bound_batch(batch, n, g + 1);
    __syncthreads();
    int beg = sbeg, end = send;

    const uint2* tu = reinterpret_cast<const uint2*>(t);
    float4 bv = *reinterpret_cast<const float4*>(b3 + fl * 4);
    float4 ps = make_float4(0.f, 0.f, 0.f, 0.f);

    for (int node = beg + slot; node < end; node += 32) {
        uint2 raw = tu[node * 16 + fl];
        float2 a0 = __half22float2(*reinterpret_cast<__half2*>(&raw.x));
        float2 a1 = __half22float2(*reinterpret_cast<__half2*>(&raw.y));
        const int* col = g_colp + node * CAP;
        int cnt = g_deg[node];
        for (int e = 0; e < cnt; ++e) {
            int s = col[e];
            uint2 r = tu[s * 16 + fl];
            float2 f0 = __half22float2(*reinterpret_cast<__half2*>(&r.x));
            float2 f1 = __half22float2(*reinterpret_cast<__half2*>(&r.y));
            a0.x += f0.x; a0.y += f0.y;
            a1.x += f1.x; a1.y += f1.y;
        }
        float d = rsqrtf((float)(cnt + 1));
        ps.x += fmaxf(d * a0.x + bv.x, 0.f);
        ps.y += fmaxf(d * a0.y + bv.y, 0.f);
        ps.z += fmaxf(d * a1.x + bv.z, 0.f);
        ps.w += fmaxf(d * a1.y + bv.w, 0.f);
    }
    *reinterpret_cast<float4*>(&psum[slot][fl * 4]) = ps;
    __syncthreads();

    if (tid < 64) {
        float s = 0.f;
#pragma unroll
        for (int w = 0; w < 32; ++w) s += psum[w][tid];
        int cnt = end - beg;
        pooled[tid] = s / (float)max(cnt, 1);
    }
    __syncthreads();

    if (tid < 64) {
        float a = lin1b[tid];
#pragma unroll
        for (int k = 0; k < 64; ++k) a += pooled[k] * lin1W[k * 64 + tid];
        h1[tid] = fmaxf(a, 0.f);
    }
    __syncthreads();

    if (tid < 10) {
        float l = lin2b[tid];
#pragma unroll
        for (int k = 0; k < 64; ++k) l += h1[k] * lin2W[k * 10 + tid];
        logits[tid] = l;
    }
    __syncthreads();

    if (tid == 0) {
        float m = logits[0];
        for (int j = 1; j < 10; ++j) m = fmaxf(m, logits[j]);
        float se = 0.f;
        for (int j = 0; j < 10; ++j) se += expf(logits[j] - m);
        lse = m + logf(se);
    }
    __syncthreads();

    if (tid < 10) out[g * 10 + tid] = logits[tid] - lse;
}

// ---------------- launch ---------------------------------------------------
extern "C" void kernel_launch(void* const* d_in, const int* in_sizes, int n_in,
                              void* d_out, int out_size) {
    const float* x     = (const float*)d_in[0];
    const void*  ei    = d_in[1];
    const void*  batch = d_in[2];
    const float* W1 = (const float*)d_in[3];
    const float* b1 = (const float*)d_in[4];
    const float* W2 = (const float*)d_in[5];
    const float* b2 = (const float*)d_in[6];
    const float* W3 = (const float*)d_in[7];
    const float* b3 = (const float*)d_in[8];
    const float* l1W = (const float*)d_in[9];
    const float* l1b = (const float*)d_in[10];
    const float* l2W = (const float*)d_in[11];
    const float* l2b = (const float*)d_in[12];
    float* out = (float*)d_out;

    const int n = in_sizes[0] / HID;
    const int e = in_sizes[1] / 2;
    const int G = out_size / 10;

    __half2* bufT = nullptr;
    float*   bufH = nullptr;
    int*     degp = nullptr;
    int*     fillp = nullptr;
    cudaGetSymbolAddress((void**)&bufT, g_bufT);
    cudaGetSymbolAddress((void**)&bufH, g_bufH);
    cudaGetSymbolAddress((void**)&degp, g_deg);
    cudaGetSymbolAddress((void**)&fillp, g_fill);

    cudaStream_t s2;
    cudaEvent_t evFork, evJoin;
    cudaStreamCreateWithFlags(&s2, cudaStreamNonBlocking);
    cudaEventCreateWithFlags(&evFork, cudaEventDisableTiming);
    cudaEventCreateWithFlags(&evJoin, cudaEventDisableTiming);

    int tpb = 256;

    // zero counters (graph-capturable memset, not an allocation)
    cudaMemsetAsync(degp, 0, (size_t)n * sizeof(int), 0);
    cudaMemsetAsync(fillp, 0, (size_t)n * sizeof(int), 0);
    detect_kernel<<<1, 256>>>((const int*)ei);

    // fork: fill (padded CSR) runs concurrently with deg -> gemm1.
    cudaEventRecord(evFork, 0);
    cudaStreamWaitEvent(s2, evFork, 0);
    fill_kernel<<<(e + tpb - 1) / tpb, tpb, 0, s2>>>(ei, e);
    cudaEventRecord(evJoin, s2);

    deg_kernel<<<(e + tpb - 1) / tpb, tpb>>>(ei, e);

    int gemm_blocks = (n + 255) / 256;
    int npairs      = (n + 1) / 2;
    int agg_blocks  = (npairs * 32 + tpb - 1) / tpb;

    gemm64_kernel<<<gemm_blocks, 256>>>(x, W1, bufT, n);    // T1

    cudaStreamWaitEvent(0, evJoin, 0);  // aggs need the CSR columns

    agg_kernel<<<agg_blocks, tpb>>>(bufT, b1, bufH, n);     // H1
    gemm64_kernel<<<gemm_blocks, 256>>>(bufH, W2, bufT, n); // T2
    agg_kernel<<<agg_blocks, tpb>>>(bufT, b2, bufH, n);     // H2
    gemm64_kernel<<<gemm_blocks, 256>>>(bufH, W3, bufT, n); // T3

    pool_mlp_kernel<<<G, 512>>>(bufT, batch, n, b3,
                                l1W, l1b, l2W, l2b, out);   // agg3+pool+MLP
}

// round 17
// speedup vs baseline: 1.3619x; 1.3619x over previous
#include <cuda_runtime.h>
#include <cuda_fp16.h>
#include <cstdint>
#include <math.h>

#define NMAX 50000
#define EMAX 800000
#define GMAX 500
#define HID  64
#define CAP  96   // padded CSR slots per node (Poisson(16) degree; P(>95)~1e-44)

// ---------------- device scratch (static, no runtime allocation) ----------
__device__ int     g_is64;             // 1 if index tensors are int64, 0 if int32
__device__ int     g_deg[NMAX];        // edge-count per node (NO self loop)
__device__ int     g_fill[NMAX];       // fill cursors
__device__ int     g_colp[NMAX * CAP]; // padded CSR
__device__ __half2 g_bufT[NMAX * 32];  // dis-scaled (h@W), fp16
__device__ __half2 g_bufH[NMAX * 32];  // relu activations, fp16

__device__ __forceinline__ int load_idx(const void* p, long long i) {
    if (g_is64) return (int)((const long long*)p)[i];
    return ((const int*)p)[i];
}

// ---------------- index dtype detection (1 block) ---------------------------
__global__ void detect_kernel(const int* __restrict__ ei32) {
    __shared__ int acc[256];
    int t = threadIdx.x;
    int v = 0;
    for (int k = t; k < 2048; k += 256) v |= ei32[2 * k + 1];
    acc[t] = v;
    __syncthreads();
    for (int off = 128; off > 0; off >>= 1) {
        if (t < off) acc[t] |= acc[t + off];
        __syncthreads();
    }
    if (t == 0) g_is64 = (acc[0] == 0) ? 1 : 0;
}

__global__ void deg_kernel(const void* __restrict__ ei, int e) {
    int i = blockIdx.x * blockDim.x + threadIdx.x;
    if (i < e) {
        int d = load_idx(ei, (long long)e + i);
        atomicAdd(&g_deg[d], 1);
    }
}

__global__ void fill_kernel(const void* __restrict__ ei, int e) {
    int i = blockIdx.x * blockDim.x + threadIdx.x;
    if (i >= e) return;
    int s = load_idx(ei, i);
    int d = load_idx(ei, (long long)e + i);
    int p = atomicAdd(&g_fill[d], 1);
    if (p < CAP) g_colp[d * CAP + p] = s;
}

// ---------------- HMMA GEMM: T[row] = fp16(ds * (in[row] @ W)) -------------
// mma.sync.aligned.m16n8k16.row.col.f32.f16.f16.f32 (valid on plain sm_103).
// 256 threads = 8 warps; 128 rows/CTA; warp computes a 16x64 tile.
// A [128][64] f16 and B=W^T [64][64] f16 staged in smem with pitch 72 halves
// (36 words): fragment loads hit banks (4q+i) mod 32 -> conflict-free.
#define APITCH 72   // halves
#define APW    36   // 32-bit words

template <bool FP16IN>
__global__ void __launch_bounds__(256) gemm_mma_kernel(
        const void* __restrict__ in, const float* __restrict__ W,
        __half2* __restrict__ outT, int n) {
    __shared__ __half As[128 * APITCH];
    __shared__ __half Bs[64 * APITCH];
    int tid  = threadIdx.x;
    int row0 = blockIdx.x * 128;

    // ---- A tile: 2 threads per row, 32 halves each ----
    {
        int r    = tid >> 1;         // 0..127
        int hhf  = tid & 1;          // which half of the row
        int gr   = row0 + r;
        __half* dst = As + r * APITCH + hhf * 32;
        if (gr < n) {
            if (FP16IN) {
                const uint4* src = reinterpret_cast<const uint4*>(in) + gr * 8 + hhf * 4;
#pragma unroll
                for (int c = 0; c < 4; ++c)
                    reinterpret_cast<uint4*>(dst)[c] = src[c];
            } else {
                const float4* f = reinterpret_cast<const float4*>(in) + gr * 16 + hhf * 8;
#pragma unroll
                for (int c = 0; c < 8; ++c) {
                    float4 fv = f[c];
                    __half2 h0 = __floats2half2_rn(fv.x, fv.y);
                    __half2 h1 = __floats2half2_rn(fv.z, fv.w);
                    reinterpret_cast<__half2*>(dst)[c * 2]     = h0;
                    reinterpret_cast<__half2*>(dst)[c * 2 + 1] = h1;
                }
            }
        } else {
#pragma unroll
            for (int c = 0; c < 16; ++c)
                reinterpret_cast<__half2*>(dst)[c] = __floats2half2_rn(0.f, 0.f);
        }
    }

    // ---- B tile: Bs[j][k] = W[k][j] (W^T, row-major [N][K]) ----
    for (int e2 = tid; e2 < 4096; e2 += 256) {
        int k = e2 >> 6, j = e2 & 63;
        Bs[j * APITCH + k] = __float2half(W[e2]);
    }
    __syncthreads();

    // ---- warp-tile mma ----
    int warp = tid >> 5;
    int lane = tid & 31;
    int g    = lane >> 2;   // group row 0..7
    int i4   = lane & 3;    // quad col 0..3
    int wrow = warp * 16;

    const uint32_t* Aw = reinterpret_cast<const uint32_t*>(As);
    const uint32_t* Bw = reinterpret_cast<const uint32_t*>(Bs);

    float acc[8][4];
#pragma unroll
    for (int nt = 0; nt < 8; ++nt)
#pragma unroll
        for (int c = 0; c < 4; ++c) acc[nt][c] = 0.f;

#pragma unroll
    for (int kc = 0; kc < 4; ++kc) {
        int kw = kc * 8;  // word offset of this k-chunk
        uint32_t a0 = Aw[(wrow + g)     * APW + kw + i4];
        uint32_t a1 = Aw[(wrow + g + 8) * APW + kw + i4];
        uint32_t a2 = Aw[(wrow + g)     * APW + kw + 4 + i4];
        uint32_t a3 = Aw[(wrow + g + 8) * APW + kw + 4 + i4];
#pragma unroll
        for (int nt = 0; nt < 8; ++nt) {
            uint32_t b0 = Bw[(nt * 8 + g) * APW + kw + i4];
            uint32_t b1 = Bw[(nt * 8 + g) * APW + kw + 4 + i4];
            asm volatile(
                "mma.sync.aligned.m16n8k16.row.col.f32.f16.f16.f32 "
                "{%0,%1,%2,%3}, {%4,%5,%6,%7}, {%8,%9}, {%0,%1,%2,%3};"
                : "+f"(acc[nt][0]), "+f"(acc[nt][1]),
                  "+f"(acc[nt][2]), "+f"(acc[nt][3])
                : "r"(a0), "r"(a1), "r"(a2), "r"(a3), "r"(b0), "r"(b1));
        }
    }

    // ---- epilogue: scale by rsqrt(deg+1), emit fp16 half2 ----
    int gr0 = row0 + wrow + g;        // rows for c0,c1
    int gr1 = gr0 + 8;                // rows for c2,c3
    float ds0 = (gr0 < n) ? rsqrtf((float)(g_deg[gr0] + 1)) : 0.f;
    float ds1 = (gr1 < n) ? rsqrtf((float)(g_deg[gr1] + 1)) : 0.f;
#pragma unroll
    for (int nt = 0; nt < 8; ++nt) {
        int c2 = nt * 4 + i4;         // half2 column index
        if (gr0 < n)
            outT[gr0 * 32 + c2] = __floats2half2_rn(ds0 * acc[nt][0], ds0 * acc[nt][1]);
        if (gr1 < n)
            outT[gr1 * 32 + c2] = __floats2half2_rn(ds1 * acc[nt][2], ds1 * acc[nt][3]);
    }
}

// ---------------- aggregation: 2 nodes/warp, fp16 in AND out ---------------
__global__ void agg_kernel(const __half2* __restrict__ t,
                           const float* __restrict__ bias,
                           __half2* __restrict__ outH, int n) {
    int warp = (blockIdx.x * blockDim.x + threadIdx.x) >> 5;
    int lane = threadIdx.x & 31;
    int sub  = lane >> 4;
    int fl   = lane & 15;          // features 4*fl..4*fl+3
    int node = warp * 2 + sub;
    if (node >= n) return;

    const uint2* tu = reinterpret_cast<const uint2*>(t);

    uint2 raw = tu[node * 16 + fl];
    float2 a0 = __half22float2(*reinterpret_cast<__half2*>(&raw.x));
    float2 a1 = __half22float2(*reinterpret_cast<__half2*>(&raw.y));

    const int* col = g_colp + node * CAP;
    int cnt = g_deg[node];
    for (int e = 0; e < cnt; ++e) {
        int s = col[e];
        uint2 r = tu[s * 16 + fl];
        float2 f0 = __half22float2(*reinterpret_cast<__half2*>(&r.x));
        float2 f1 = __half22float2(*reinterpret_cast<__half2*>(&r.y));
        a0.x += f0.x; a0.y += f0.y;
        a1.x += f1.x; a1.y += f1.y;
    }

    float d = rsqrtf((float)(cnt + 1));
    float4 b = *reinterpret_cast<const float4*>(bias + fl * 4);
    __half2 h0 = __floats2half2_rn(fmaxf(d * a0.x + b.x, 0.f),
                                   fmaxf(d * a0.y + b.y, 0.f));
    __half2 h1 = __floats2half2_rn(fmaxf(d * a1.x + b.z, 0.f),
                                   fmaxf(d * a1.y + b.w, 0.f));
    uint2 ov;
    ov.x = *reinterpret_cast<uint32_t*>(&h0);
    ov.y = *reinterpret_cast<uint32_t*>(&h1);
    reinterpret_cast<uint2*>(outH)[node * 16 + fl] = ov;
}

// ---------------- fused agg3 + mean pool + MLP + log_softmax ---------------
__device__ __forceinline__ int lower_bound_batch(const void* batch, int n, int key) {
    int lo = 0, hi = n;
    while (lo < hi) {
        int mid = (lo + hi) >> 1;
        if (load_idx(batch, mid) < key) lo = mid + 1;
        else hi = mid;
    }
    return lo;
}

__global__ void pool_mlp_kernel(const __half2* __restrict__ t,
                                const void* __restrict__ batch, int n,
                                const float* __restrict__ b3,
                                const float* __restrict__ lin1W,
                                const float* __restrict__ lin1b,
                                const float* __restrict__ lin2W,
                                const float* __restrict__ lin2b,
                                float* __restrict__ out) {
    int g    = blockIdx.x;
    int tid  = threadIdx.x;  // 512
    int warp = tid >> 5;
    int lane = tid & 31;
    int sub  = lane >> 4;
    int fl   = lane & 15;
    int slot = warp * 2 + sub;  // 0..31

    __shared__ float psum[32][64];
    __shared__ float pooled[64];
    __shared__ float h1[64];
    __shared__ float logits[10];
    __shared__ float lse;
    __shared__ int   sbeg, send;

    if (tid == 0) sbeg = lower_bound_batch(batch, n, g);
    if (tid == 32) send = lower_bound_batch(batch, n, g + 1);
    __syncthreads();
    int beg = sbeg, end = send;

    const uint2* tu = reinterpret_cast<const uint2*>(t);
    float4 bv = *reinterpret_cast<const float4*>(b3 + fl * 4);
    float4 ps = make_float4(0.f, 0.f, 0.f, 0.f);

    for (int node = beg + slot; node < end; node += 32) {
        uint2 raw = tu[node * 16 + fl];
        float2 a0 = __half22float2(*reinterpret_cast<__half2*>(&raw.x));
        float2 a1 = __half22float2(*reinterpret_cast<__half2*>(&raw.y));
        const int* col = g_colp + node * CAP;
        int cnt = g_deg[node];
        for (int e = 0; e < cnt; ++e) {
            int s = col[e];
            uint2 r = tu[s * 16 + fl];
            float2 f0 = __half22float2(*reinterpret_cast<__half2*>(&r.x));
            float2 f1 = __half22float2(*reinterpret_cast<__half2*>(&r.y));
            a0.x += f0.x; a0.y += f0.y;
            a1.x += f1.x; a1.y += f1.y;
        }
        float d = rsqrtf((float)(cnt + 1));
        ps.x += fmaxf(d * a0.x + bv.x, 0.f);
        ps.y += fmaxf(d * a0.y + bv.y, 0.f);
        ps.z += fmaxf(d * a1.x + bv.z, 0.f);
        ps.w += fmaxf(d * a1.y + bv.w, 0.f);
    }
    *reinterpret_cast<float4*>(&psum[slot][fl * 4]) = ps;
    __syncthreads();

    if (tid < 64) {
        float s = 0.f;
#pragma unroll
        for (int w = 0; w < 32; ++w) s += psum[w][tid];
        int cnt = end - beg;
        pooled[tid] = s / (float)max(cnt, 1);
    }
    __syncthreads();

    if (tid < 64) {
        float a = lin1b[tid];
#pragma unroll
        for (int k = 0; k < 64; ++k) a += pooled[k] * lin1W[k * 64 + tid];
        h1[tid] = fmaxf(a, 0.f);
    }
    __syncthreads();

    if (tid < 10) {
        float l = lin2b[tid];
#pragma unroll
        for (int k = 0; k < 64; ++k) l += h1[k] * lin2W[k * 10 + tid];
        logits[tid] = l;
    }
    __syncthreads();

    if (tid == 0) {
        float m = logits[0];
        for (int j = 1; j < 10; ++j) m = fmaxf(m, logits[j]);
        float se = 0.f;
        for (int j = 0; j < 10; ++j) se += expf(logits[j] - m);
        lse = m + logf(se);
    }
    __syncthreads();

    if (tid < 10) out[g * 10 + tid] = logits[tid] - lse;
}

// ---------------- launch ---------------------------------------------------
extern "C" void kernel_launch(void* const* d_in, const int* in_sizes, int n_in,
                              void* d_out, int out_size) {
    const float* x     = (const float*)d_in[0];
    const void*  ei    = d_in[1];
    const void*  batch = d_in[2];
    const float* W1 = (const float*)d_in[3];
    const float* b1 = (const float*)d_in[4];
    const float* W2 = (const float*)d_in[5];
    const float* b2 = (const float*)d_in[6];
    const float* W3 = (const float*)d_in[7];
    const float* b3 = (const float*)d_in[8];
    const float* l1W = (const float*)d_in[9];
    const float* l1b = (const float*)d_in[10];
    const float* l2W = (const float*)d_in[11];
    const float* l2b = (const float*)d_in[12];
    float* out = (float*)d_out;

    const int n = in_sizes[0] / HID;
    const int e = in_sizes[1] / 2;
    const int G = out_size / 10;

    __half2* bufT = nullptr;
    __half2* bufH = nullptr;
    int*     degp = nullptr;
    int*     fillp = nullptr;
    cudaGetSymbolAddress((void**)&bufT, g_bufT);
    cudaGetSymbolAddress((void**)&bufH, g_bufH);
    cudaGetSymbolAddress((void**)&degp, g_deg);
    cudaGetSymbolAddress((void**)&fillp, g_fill);

    cudaStream_t s2;
    cudaEvent_t evFork, evJoin;
    cudaStreamCreateWithFlags(&s2, cudaStreamNonBlocking);
    cudaEventCreateWithFlags(&evFork, cudaEventDisableTiming);
    cudaEventCreateWithFlags(&evJoin, cudaEventDisableTiming);

    int tpb = 256;

    cudaMemsetAsync(degp, 0, (size_t)n * sizeof(int), 0);
    cudaMemsetAsync(fillp, 0, (size_t)n * sizeof(int), 0);
    detect_kernel<<<1, 256>>>((const int*)ei);

    // fork: fill (padded CSR) runs concurrently with deg -> gemm1.
    cudaEventRecord(evFork, 0);
    cudaStreamWaitEvent(s2, evFork, 0);
    fill_kernel<<<(e + tpb - 1) / tpb, tpb, 0, s2>>>(ei, e);
    cudaEventRecord(evJoin, s2);

    deg_kernel<<<(e + tpb - 1) / tpb, tpb>>>(ei, e);

    int gemm_blocks = (n + 127) / 128;
    int npairs      = (n + 1) / 2;
    int agg_blocks  = (npairs * 32 + tpb - 1) / tpb;

    gemm_mma_kernel<false><<<gemm_blocks, 256>>>(x, W1, bufT, n);   // T1

    cudaStreamWaitEvent(0, evJoin, 0);  // aggs need the CSR columns

    agg_kernel<<<agg_blocks, tpb>>>(bufT, b1, bufH, n);             // H1
    gemm_mma_kernel<true><<<gemm_blocks, 256>>>(bufH, W2, bufT, n); // T2
    agg_kernel<<<agg_blocks, tpb>>>(bufT, b2, bufH, n);             // H2
    gemm_mma_kernel<true><<<gemm_blocks, 256>>>(bufH, W3, bufT, n); // T3

    pool_mlp_kernel<<<G, 512>>>(bufT, batch, n, b3,
                                l1W, l1b, l2W, l2b, out);   // agg3+pool+MLP
}